// round 15
// baseline (speedup 1.0000x reference)
#include <cuda_runtime.h>
#include <cuda_bf16.h>

typedef unsigned long long u64;
typedef unsigned u32;

#define ND 20000
#define NG 20000
#define NC 10000
#define BB 4096

__device__ float g_E_drug[ND * 128];
__device__ float g_E_gene[NG * 128];
__device__ float g_E_cell[NC * 128];
__device__ float g_XW[6 * BB * 10 * 384];
__device__ float g_S[6 * BB * 128];
// transposed bf16-split weights [N][K]: [d | g | c | x(6) | u(6)]
#define WOFF_D 0
#define WOFF_G 262144
#define WOFF_C 393216
#define WOFF_X 458752
#define WOFF_U 753664
__device__ __nv_bfloat16 g_WT_hi[1048576];
__device__ __nv_bfloat16 g_WT_lo[1048576];

// ---------------- scalar helpers ----------------
__device__ __forceinline__ float sigmf(float x) {
    return __fdividef(1.f, 1.f + __expf(-x));
}
__device__ __forceinline__ float tanh_fast(float x) {
    float ax = fabsf(x);
    float e = __expf(-2.f * ax);
    return copysignf(__fdividef(1.f - e, 1.f + e), x);
}
// {lo=bf16_trunc(a_fp32bits), hi=bf16_trunc(b_fp32bits)}
__device__ __forceinline__ u32 hipack(u32 a, u32 b) {
    u32 d;
    asm("prmt.b32 %0, %1, %2, 0x7632;" : "=r"(d) : "r"(a), "r"(b));
    return d;
}
#define PACKBF2(r, a, b) \
    asm("cvt.rn.satfinite.bf16x2.f32 %0, %1, %2;" : "=r"(r) : "f"(b), "f"(a))

#define MMA_BF16(c, a0, a1, a2, a3, b0, b1) \
    asm volatile("mma.sync.aligned.m16n8k16.row.col.f32.bf16.bf16.f32 " \
        "{%0,%1,%2,%3}, {%4,%5,%6,%7}, {%8,%9}, {%0,%1,%2,%3};" \
        : "+f"((c)[0]), "+f"((c)[1]), "+f"((c)[2]), "+f"((c)[3]) \
        : "r"(a0), "r"(a1), "r"(a2), "r"(a3), "r"(b0), "r"(b1))

// ---------------- 0) transpose + split ALL weights (one launch) --------------
__global__ void wsplit_all(const float* __restrict__ Wd, const float* __restrict__ Wg,
                           const float* __restrict__ Wc, const float* __restrict__ gW,
                           const float* __restrict__ gU)
{
    int y = blockIdx.y;
    const float* src;
    int dstoff, K, N;
    if (y == 0)      { src = Wd; dstoff = WOFF_D; K = 2048; N = 128; }
    else if (y == 1) { src = Wg; dstoff = WOFF_G; K = 1024; N = 128; }
    else if (y == 2) { src = Wc; dstoff = WOFF_C; K = 512;  N = 128; }
    else if (y < 9)  { int lt = y - 3; src = gW + (size_t)lt * 49152;
                       dstoff = WOFF_X + lt * 49152; K = 128; N = 384; }
    else             { int lt = y - 9; src = gU + (size_t)lt * 49152;
                       dstoff = WOFF_U + lt * 49152; K = 128; N = 384; }
    __nv_bfloat16* hi = g_WT_hi + dstoff;
    __nv_bfloat16* lo = g_WT_lo + dstoff;
    int total = K * N;
    for (int i = blockIdx.x * blockDim.x + threadIdx.x; i < total; i += gridDim.x * blockDim.x) {
        int k = i / N, n = i - k * N;
        float w = src[i];
        u32 u = __float_as_uint(w);
        __nv_bfloat16_raw hr; hr.x = (unsigned short)(u >> 16);
        hi[(size_t)n * K + k] = __nv_bfloat16(hr);
        lo[(size_t)n * K + k] = __float2bfloat16(w - __uint_as_float(u & 0xffff0000u));
    }
}

// ---------------- 1) proj: fragment-major smem, 1 LDS.128 per fragment -------
// sAh/sAl[((mt*4+ks)*32+lane)*4+comp], comp=half+2*khalf.
// sB[((j*4+ks)*32+lane)*4 + {bh0,bh1,bl0,bl1}].
__global__ __launch_bounds__(256, 2) void proj_mma(
    const float* __restrict__ drug, const float* __restrict__ gene,
    const float* __restrict__ cell,
    const float* __restrict__ bd, const float* __restrict__ bg,
    const float* __restrict__ bc)
{
    extern __shared__ u32 sm32[];
    u32* sAh = sm32;               // 4096
    u32* sAl = sAh + 4096;         // 4096
    u32* sB  = sAl + 4096;         // 8192

    int bx = blockIdx.x;
    const float *F, *bias;
    float* E;
    int N, K, woff, bstart;
    if (bx < 157)      { F = drug; bias = bd; E = g_E_drug; N = ND; K = 2048; woff = WOFF_D; bstart = bx; }
    else if (bx < 314) { F = gene; bias = bg; E = g_E_gene; N = NG; K = 1024; woff = WOFF_G; bstart = bx - 157; }
    else               { F = cell; bias = bc; E = g_E_cell; N = NC; K = 512;  woff = WOFF_C; bstart = bx - 314; }
    const __nv_bfloat16* WTh = g_WT_hi + woff;
    const __nv_bfloat16* WTl = g_WT_lo + woff;

    int tid = threadIdx.x, wm = tid >> 5, lane = tid & 31;
    int g = lane >> 2, t = lane & 3;
    int row0 = bstart * 128;

    float acc[16][4];
#pragma unroll
    for (int j = 0; j < 16; j++)
#pragma unroll
        for (int q = 0; q < 4; q++) acc[j][q] = 0.f;

    int srow = tid >> 1, skh = (tid & 1) * 32;
    int sk2 = skh >> 1;                 // base u32 col within k-tile (0 or 16)
    int aclamp = row0 + srow < N ? row0 + srow : N - 1;
    const float* Abase = F + (size_t)aclamp * K;
    // A scatter coords
    int amt = srow >> 4, arr = srow & 15, ag = arr & 7, ahalf = arr >> 3;
    // B coords (srow as n)
    int bj = srow >> 3, bg2 = srow & 7;
    int bks0 = (tid & 1) * 2;

    for (int kc = 0; kc < K; kc += 64) {
        __syncthreads();
        {   // stage A: fp32 -> hi/lo, scatter into fragment slots
            const float4* src = (const float4*)(Abase + kc + skh);
#pragma unroll
            for (int i = 0; i < 8; i++) {
                float4 f = src[i];
                u32 ux = __float_as_uint(f.x), uy = __float_as_uint(f.y);
                u32 uz = __float_as_uint(f.z), uw = __float_as_uint(f.w);
                u32 h0 = hipack(ux, uy), h1 = hipack(uz, uw);
                float lx = f.x - __uint_as_float(ux & 0xffff0000u);
                float ly = f.y - __uint_as_float(uy & 0xffff0000u);
                float lz = f.z - __uint_as_float(uz & 0xffff0000u);
                float lw = f.w - __uint_as_float(uw & 0xffff0000u);
                u32 l0, l1;
                PACKBF2(l0, lx, ly);
                PACKBF2(l1, lz, lw);
                int kul = sk2 + 2 * i;
                int ks = kul >> 3, tq = kul & 7;
                u32 s0 = (u32)(((amt * 4 + ks) * 32 + ag * 4 + (tq & 3)) * 4 + ahalf + 2 * (tq >> 2));
                kul++;
                ks = kul >> 3; tq = kul & 7;
                u32 s1 = (u32)(((amt * 4 + ks) * 32 + ag * 4 + (tq & 3)) * 4 + ahalf + 2 * (tq >> 2));
                sAh[s0] = h0; sAl[s0] = l0;
                sAh[s1] = h1; sAl[s1] = l1;
            }
        }
        {   // stage B: assemble full fragments, STS.128
            const uint4* bh = (const uint4*)(WTh + (size_t)srow * K + kc + skh);
            const uint4* bl = (const uint4*)(WTl + (size_t)srow * K + kc + skh);
            uint4 vh[4], vl[4];
#pragma unroll
            for (int i = 0; i < 4; i++) { vh[i] = bh[i]; vl[i] = bl[i]; }
            const u32* hi16 = (const u32*)vh;
            const u32* lo16 = (const u32*)vl;
#pragma unroll
            for (int ksl = 0; ksl < 2; ksl++)
#pragma unroll
                for (int tt = 0; tt < 4; tt++) {
                    uint4 v;
                    v.x = hi16[ksl * 8 + tt];
                    v.y = hi16[ksl * 8 + 4 + tt];
                    v.z = lo16[ksl * 8 + tt];
                    v.w = lo16[ksl * 8 + 4 + tt];
                    *(uint4*)(sB + (u32)(((bj * 4 + bks0 + ksl) * 32 + bg2 * 4 + tt) * 4)) = v;
                }
        }
        __syncthreads();

#pragma unroll
        for (int ks = 0; ks < 4; ks++) {
            uint4 afh = *(const uint4*)(sAh + (u32)(((wm * 4 + ks) * 32 + lane) * 4));
            uint4 afl = *(const uint4*)(sAl + (u32)(((wm * 4 + ks) * 32 + lane) * 4));
#pragma unroll
            for (int j = 0; j < 16; j++) {
                uint4 bf = *(const uint4*)(sB + (u32)(((j * 4 + ks) * 32 + lane) * 4));
                MMA_BF16(acc[j], afh.x, afh.y, afh.z, afh.w, bf.x, bf.y);
                MMA_BF16(acc[j], afl.x, afl.y, afl.z, afl.w, bf.x, bf.y);
                MMA_BF16(acc[j], afh.x, afh.y, afh.z, afh.w, bf.z, bf.w);
            }
        }
    }

    int r0 = row0 + wm * 16 + g;
#pragma unroll
    for (int j = 0; j < 16; j++) {
        int col = j * 8 + 2 * t;
        float bx2 = bias[col], by = bias[col + 1];
        if (r0 < N)
            *(float2*)(E + (size_t)r0 * 128 + col) =
                make_float2(acc[j][0] + bx2, acc[j][1] + by);
        if (r0 + 8 < N)
            *(float2*)(E + (size_t)(r0 + 8) * 128 + col) =
                make_float2(acc[j][2] + bx2, acc[j][3] + by);
    }
}

// ---------------- 2) xw: layer-merged + fragment-major -----------------------
// sAh/sAl[((mt*8+ks)*32+lane)*4+comp]; sB[((j*8+ks)*32+lane)*4 + 4 comps].
__global__ __launch_bounds__(256, 2) void xw_mma(
    const float* __restrict__ gruB,
    const int* __restrict__ nd, const int* __restrict__ ng,
    const int* __restrict__ pnc)
{
    extern __shared__ u32 sm32[];
    u32* sAh = sm32;               // 8192
    u32* sAl = sAh + 8192;         // 8192
    u32* sB  = sAl + 8192;         // 8192

    int tid = threadIdx.x, wm = tid >> 5, lane = tid & 31;
    int g = lane >> 2, t = lane & 3;
    int t3 = blockIdx.y;
    const int* nbr = (t3 == 0) ? nd : (t3 == 1) ? ng : pnc;
    const float* Etab = (t3 == 0) ? g_E_drug : (t3 == 1) ? g_E_gene : g_E_cell;
    int row0 = blockIdx.x * 128;

    {   // stage A (gathered, K=128) ONCE, fragment-major
        int srow = tid >> 1, skh = (tid & 1) * 64;
        int sk2 = skh >> 1;        // 0 or 32
        int id = nbr[row0 + srow];
        bool v = (id >= 0);
        const float4* src = (const float4*)(Etab + (size_t)(v ? id : 0) * 128 + skh);
        int amt = srow >> 4, arr = srow & 15, ag = arr & 7, ahalf = arr >> 3;
#pragma unroll
        for (int i = 0; i < 16; i++) {
            float4 f = v ? src[i] : make_float4(0.f, 0.f, 0.f, 0.f);
            u32 ux = __float_as_uint(f.x), uy = __float_as_uint(f.y);
            u32 uz = __float_as_uint(f.z), uw = __float_as_uint(f.w);
            u32 h0 = hipack(ux, uy), h1 = hipack(uz, uw);
            float lx = f.x - __uint_as_float(ux & 0xffff0000u);
            float ly = f.y - __uint_as_float(uy & 0xffff0000u);
            float lz = f.z - __uint_as_float(uz & 0xffff0000u);
            float lw = f.w - __uint_as_float(uw & 0xffff0000u);
            u32 l0, l1;
            PACKBF2(l0, lx, ly);
            PACKBF2(l1, lz, lw);
            int kul = sk2 + 2 * i;
            int ks = kul >> 3, tq = kul & 7;
            u32 s0 = (u32)(((amt * 8 + ks) * 32 + ag * 4 + (tq & 3)) * 4 + ahalf + 2 * (tq >> 2));
            kul++;
            ks = kul >> 3; tq = kul & 7;
            u32 s1 = (u32)(((amt * 8 + ks) * 32 + ag * 4 + (tq & 3)) * 4 + ahalf + 2 * (tq >> 2));
            sAh[s0] = h0; sAl[s0] = l0;
            sAh[s1] = h1; sAl[s1] = l1;
        }
    }

    int brow = tid >> 2, kq = (tid & 3) * 32;
    int bj = brow >> 3, bg2 = brow & 7;
    int bks0 = (tid & 3) * 2;

#pragma unroll
    for (int l = 0; l < 2; l++) {
        int lt = l * 3 + t3;
        const __nv_bfloat16* WTh = g_WT_hi + WOFF_X + lt * 49152;
        const __nv_bfloat16* WTl = g_WT_lo + WOFF_X + lt * 49152;
        const float* bias = gruB + lt * 384;
        float* out = g_XW + (size_t)lt * 40960 * 384;

        for (int ncb = 0; ncb < 6; ncb++) {
            __syncthreads();
            {   // stage B chunk fragment-major (STS.128 assembled fragments)
                const uint4* bh = (const uint4*)(WTh + (size_t)(ncb * 64 + brow) * 128 + kq);
                const uint4* bl = (const uint4*)(WTl + (size_t)(ncb * 64 + brow) * 128 + kq);
                uint4 vh[4], vl[4];
#pragma unroll
                for (int i = 0; i < 4; i++) { vh[i] = bh[i]; vl[i] = bl[i]; }
                const u32* hi16 = (const u32*)vh;
                const u32* lo16 = (const u32*)vl;
#pragma unroll
                for (int ksl = 0; ksl < 2; ksl++)
#pragma unroll
                    for (int tt = 0; tt < 4; tt++) {
                        uint4 v;
                        v.x = hi16[ksl * 8 + tt];
                        v.y = hi16[ksl * 8 + 4 + tt];
                        v.z = lo16[ksl * 8 + tt];
                        v.w = lo16[ksl * 8 + 4 + tt];
                        *(uint4*)(sB + (u32)(((bj * 8 + bks0 + ksl) * 32 + bg2 * 4 + tt) * 4)) = v;
                    }
            }
            __syncthreads();

            float acc[8][4];
#pragma unroll
            for (int j = 0; j < 8; j++)
#pragma unroll
                for (int q = 0; q < 4; q++) acc[j][q] = 0.f;

#pragma unroll
            for (int ks = 0; ks < 8; ks++) {
                uint4 afh = *(const uint4*)(sAh + (u32)(((wm * 8 + ks) * 32 + lane) * 4));
                uint4 afl = *(const uint4*)(sAl + (u32)(((wm * 8 + ks) * 32 + lane) * 4));
#pragma unroll
                for (int j = 0; j < 8; j++) {
                    uint4 bf = *(const uint4*)(sB + (u32)(((j * 8 + ks) * 32 + lane) * 4));
                    MMA_BF16(acc[j], afh.x, afh.y, afh.z, afh.w, bf.x, bf.y);
                    MMA_BF16(acc[j], afl.x, afl.y, afl.z, afl.w, bf.x, bf.y);
                    MMA_BF16(acc[j], afh.x, afh.y, afh.z, afh.w, bf.z, bf.w);
                }
            }

            int r0 = row0 + wm * 16 + g;
#pragma unroll
            for (int j = 0; j < 8; j++) {
                int col = ncb * 64 + j * 8 + 2 * t;
                float bx = bias[col], by = bias[col + 1];
                *(float2*)(out + (size_t)r0 * 384 + col) =
                    make_float2(acc[j][0] + bx, acc[j][1] + by);
                *(float2*)(out + (size_t)(r0 + 8) * 384 + col) =
                    make_float2(acc[j][2] + bx, acc[j][3] + by);
            }
        }
    }
}

// ---------------- 3) GRU recurrence — fragment-major U + H (R14 passing) -----
__global__ __launch_bounds__(512, 1) void gru_mma(
    const int* __restrict__ nd, const int* __restrict__ ng,
    const int* __restrict__ pnc)
{
    extern __shared__ u32 sg[];
    u32* sU  = sg;                  // 49152 u32 (U hi+lo fragment-major)
    u32* sAh = sU + 49152;          // 2048 (H hi fragment-major)
    u32* sAl = sAh + 2048;          // 2048
    float* sM = (float*)(sAl + 2048);   // 320
    float* sCnt = sM + 320;             // 32

    int tid = threadIdx.x, wm = tid >> 5, lane = tid & 31;
    int g = lane >> 2, t = lane & 3;
    int lt = blockIdx.y, t3 = lt % 3;
    const int* nbr = (t3 == 0) ? nd : (t3 == 1) ? ng : pnc;
    int b0 = blockIdx.x * 32;
    const uint4* UTh = (const uint4*)(g_WT_hi + WOFF_U + lt * 49152);
    const uint4* UTl = (const uint4*)(g_WT_lo + WOFF_U + lt * 49152);

    for (int i = tid; i < 6144; i += 512) {
        int n = i >> 4;
        int q = i & 15;
        uint4 vh = UTh[i];
        uint4 vl = UTl[i];
        int n8 = n >> 3, gg = n & 7, ks = q >> 1, c = q & 1;
        u32 base = (u32)((n8 * 8 + ks) * 32 + gg * 4) * 4 + c;
        sU[base + 0]  = vh.x; sU[base + 4]  = vh.y;
        sU[base + 8]  = vh.z; sU[base + 12] = vh.w;
        sU[base + 2]  = vl.x; sU[base + 6]  = vl.y;
        sU[base + 10] = vl.z; sU[base + 14] = vl.w;
    }
    for (int i = tid; i < 320; i += 512) {
        int rr = i / 10, s = i % 10;
        sM[i] = (nbr[(size_t)(b0 + rr) * 10 + s] >= 0) ? 1.f : 0.f;
    }
    for (int i = tid; i < 2048; i += 512) { sAh[i] = 0u; sAl[i] = 0u; }
    __syncthreads();
    if (tid < 32) {
        float c = 0.f;
        for (int s = 0; s < 10; s++) c += sM[tid * 10 + s];
        sCnt[tid] = fmaxf(c, 1.f);
    }
    __syncthreads();

    int ksp = wm >> 1;
    int cb  = (wm & 1) * 2;

    float hreg[2][4], msum[2][4];
#pragma unroll
    for (int mi = 0; mi < 2; mi++)
#pragma unroll
        for (int q = 0; q < 4; q++) { hreg[mi][q] = 0.f; msum[mi][q] = 0.f; }

    for (int s = 0; s < 10; s++) {
        float2 xz[2][2], xr[2][2], xn[2][2];
        int d0 = 8 * wm + 2 * t;
#pragma unroll
        for (int mi = 0; mi < 2; mi++)
#pragma unroll
            for (int rh = 0; rh < 2; rh++) {
                int lrow = mi * 16 + g + rh * 8;
                const float* xwb = g_XW +
                    ((size_t)lt * 40960 + (size_t)(b0 + lrow) * 10 + s) * 384;
                xz[mi][rh] = *(const float2*)(xwb + d0);
                xr[mi][rh] = *(const float2*)(xwb + 128 + d0);
                xn[mi][rh] = *(const float2*)(xwb + 256 + d0);
            }

        float acc[2][3][4];
#pragma unroll
        for (int mi = 0; mi < 2; mi++)
#pragma unroll
            for (int j = 0; j < 3; j++)
#pragma unroll
                for (int q = 0; q < 4; q++) acc[mi][j][q] = 0.f;

#pragma unroll
        for (int ks = 0; ks < 8; ks++) {
            uint4 afh[2], afl[2];
#pragma unroll
            for (int mi = 0; mi < 2; mi++) {
                u32 ab = (u32)((mi * 8 + ks) * 32 + lane) * 4;
                afh[mi] = *(const uint4*)(sAh + ab);
                afl[mi] = *(const uint4*)(sAl + ab);
            }
#pragma unroll
            for (int j = 0; j < 3; j++) {
                int n8 = j * 16 + wm;
                uint4 bf = *(const uint4*)(sU + (u32)((n8 * 8 + ks) * 32 + lane) * 4);
#pragma unroll
                for (int mi = 0; mi < 2; mi++) {
                    MMA_BF16(acc[mi][j], afh[mi].x, afh[mi].y, afh[mi].z, afh[mi].w, bf.x, bf.y);
                    MMA_BF16(acc[mi][j], afl[mi].x, afl[mi].y, afl[mi].z, afl[mi].w, bf.x, bf.y);
                    MMA_BF16(acc[mi][j], afh[mi].x, afh[mi].y, afh[mi].z, afh[mi].w, bf.z, bf.w);
                }
            }
        }
        __syncthreads();

#pragma unroll
        for (int mi = 0; mi < 2; mi++)
#pragma unroll
            for (int rh = 0; rh < 2; rh++) {
                int q0 = rh * 2;
                int lrow = mi * 16 + g + rh * 8;
                float2 vz = xz[mi][rh], vr = xr[mi][rh], vn = xn[mi][rh];
                float z0 = sigmf(vz.x + acc[mi][0][q0]);
                float z1 = sigmf(vz.y + acc[mi][0][q0 + 1]);
                float r0 = sigmf(vr.x + acc[mi][1][q0]);
                float r1 = sigmf(vr.y + acc[mi][1][q0 + 1]);
                float n0 = tanh_fast(vn.x + r0 * acc[mi][2][q0]);
                float n1 = tanh_fast(vn.y + r1 * acc[mi][2][q0 + 1]);
                float h0 = (1.f - z0) * n0 + z0 * hreg[mi][q0];
                float h1 = (1.f - z1) * n1 + z1 * hreg[mi][q0 + 1];
                hreg[mi][q0] = h0;
                hreg[mi][q0 + 1] = h1;
                float mk = sM[lrow * 10 + s];
                msum[mi][q0]     += mk * h0;
                msum[mi][q0 + 1] += mk * h1;
                u32 u0 = __float_as_uint(h0), u1 = __float_as_uint(h1);
                u32 hi = hipack(u0, u1);
                float l0f = h0 - __uint_as_float(u0 & 0xffff0000u);
                float l1f = h1 - __uint_as_float(u1 & 0xffff0000u);
                u32 lo;
                PACKBF2(lo, l0f, l1f);
                u32 hidx = (u32)((mi * 8 + ksp) * 32 + lane) * 4 + cb + rh;
                sAh[hidx] = hi;
                sAl[hidx] = lo;
            }
        __syncthreads();
    }

    int d0 = 8 * wm + 2 * t;
#pragma unroll
    for (int mi = 0; mi < 2; mi++)
#pragma unroll
        for (int rh = 0; rh < 2; rh++) {
            int q0 = rh * 2;
            int lrow = mi * 16 + g + rh * 8;
            float invc = 1.f / sCnt[lrow];
            *(float2*)(g_S + ((size_t)lt * BB + b0 + lrow) * 128 + d0) =
                make_float2(msum[mi][q0] * invc, msum[mi][q0 + 1] * invc);
        }
}

// ---------------- 4) attention combine — shuffle reductions ------------------
__global__ __launch_bounds__(128) void final_kernel(
    const float* __restrict__ att, const int* __restrict__ ids,
    float* __restrict__ out)
{
    __shared__ float red[20];
    __shared__ float sC[3][128];
    int b = blockIdx.x, d = threadIdx.x;
    int w = d >> 5, lane = d & 31;
    float h = g_E_drug[(size_t)ids[b] * 128 + d];
#pragma unroll
    for (int l = 0; l < 2; l++) {
        for (int t = 0; t < 3; t++)
            sC[t][d] = g_S[((size_t)(l * 3 + t) * BB + b) * 128 + d];
        __syncthreads();
        float a1 = att[l * 256 + d], a2 = att[l * 256 + 128 + d];
        float p0 = h * a1, p1 = h * a2;
        float p2 = sC[0][d] * a2, p3 = sC[1][d] * a2, p4 = sC[2][d] * a2;
#pragma unroll
        for (int st = 16; st > 0; st >>= 1) {
            p0 += __shfl_xor_sync(0xffffffffu, p0, st);
            p1 += __shfl_xor_sync(0xffffffffu, p1, st);
            p2 += __shfl_xor_sync(0xffffffffu, p2, st);
            p3 += __shfl_xor_sync(0xffffffffu, p3, st);
            p4 += __shfl_xor_sync(0xffffffffu, p4, st);
        }
        if (lane == 0) {
            red[w] = p0; red[4 + w] = p1; red[8 + w] = p2;
            red[12 + w] = p3; red[16 + w] = p4;
        }
        __syncthreads();
        float dh1 = red[0] + red[1] + red[2] + red[3];
        float dh2 = red[4] + red[5] + red[6] + red[7];
        float c1 = red[8] + red[9] + red[10] + red[11];
        float c2 = red[12] + red[13] + red[14] + red[15];
        float c3 = red[16] + red[17] + red[18] + red[19];
        float e0 = dh1 + dh2, e1 = dh1 + c1, e2 = dh1 + c2, e3 = dh1 + c3;
        e0 = e0 > 0.f ? e0 : 0.01f * e0;
        e1 = e1 > 0.f ? e1 : 0.01f * e1;
        e2 = e2 > 0.f ? e2 : 0.01f * e2;
        e3 = e3 > 0.f ? e3 : 0.01f * e3;
        float mx = fmaxf(fmaxf(e0, e1), fmaxf(e2, e3));
        float w0 = __expf(e0 - mx), w1 = __expf(e1 - mx);
        float w2 = __expf(e2 - mx), w3 = __expf(e3 - mx);
        float inv = __fdividef(1.f, w0 + w1 + w2 + w3);
        h = (w0 * h + w1 * sC[0][d] + w2 * sC[1][d] + w3 * sC[2][d]) * inv;
        __syncthreads();
    }
    out[(size_t)b * 128 + d] = h;
}

// ---------------- launch ----------------
extern "C" void kernel_launch(void* const* d_in, const int* in_sizes, int n_in,
                              void* d_out, int out_size)
{
    const float* drug = (const float*)d_in[0];
    const float* gene = (const float*)d_in[1];
    const float* cell = (const float*)d_in[2];
    const float* Wd = (const float*)d_in[3];
    const float* bd = (const float*)d_in[4];
    const float* Wg = (const float*)d_in[5];
    const float* bg = (const float*)d_in[6];
    const float* Wc = (const float*)d_in[7];
    const float* bc = (const float*)d_in[8];
    const float* gW = (const float*)d_in[9];
    const float* gU = (const float*)d_in[10];
    const float* gb = (const float*)d_in[11];
    const float* att = (const float*)d_in[12];
    const int* ids = (const int*)d_in[13];
    const int* nd = (const int*)d_in[14];
    const int* ng = (const int*)d_in[15];
    const int* nc = (const int*)d_in[16];
    float* out = (float*)d_out;

    const int PROJ_SMEM = 16384 * 4;                    // 65536
    const int XW_SMEM   = 24576 * 4;                    // 98304
    const int GRUM_SMEM = (49152 + 2 * 2048 + 352) * 4; // 214400
    cudaFuncSetAttribute(proj_mma, cudaFuncAttributeMaxDynamicSharedMemorySize, PROJ_SMEM);
    cudaFuncSetAttribute(xw_mma, cudaFuncAttributeMaxDynamicSharedMemorySize, XW_SMEM);
    cudaFuncSetAttribute(gru_mma, cudaFuncAttributeMaxDynamicSharedMemorySize, GRUM_SMEM);

    // 0) weight transpose + bf16 split (all, one launch)
    wsplit_all<<<dim3(32, 15), 256>>>(Wd, Wg, Wc, gW, gU);

    // 1) project all 3 tables (fragment-major)
    proj_mma<<<393, 256, PROJ_SMEM>>>(drug, gene, cell, bd, bg, bc);

    // 2) XW = gathered E @ gru_W + gru_b (layer-merged, fragment-major)
    xw_mma<<<dim3(320, 3), 256, XW_SMEM>>>(gb, nd, ng, nc);

    // 3) GRU recurrence + masked mean (fragment-major U + H)
    gru_mma<<<dim3(BB / 32, 6), 512, GRUM_SMEM>>>(nd, ng, nc);

    // 4) attention combine + output
    final_kernel<<<BB, 128>>>(att, ids, out);
}

// round 16
// speedup vs baseline: 1.0606x; 1.0606x over previous
#include <cuda_runtime.h>
#include <cuda_bf16.h>

typedef unsigned long long u64;
typedef unsigned u32;

#define ND 20000
#define NG 20000
#define NC 10000
#define BB 4096

__device__ float g_E_drug[ND * 128];
__device__ float g_E_gene[NG * 128];
__device__ float g_E_cell[NC * 128];
__device__ float g_XW[6 * BB * 10 * 384];
__device__ float g_S[6 * BB * 128];
// transposed bf16-split weights [N][K]: [d | g | c | x(6) | u(6)]
#define WOFF_D 0
#define WOFF_G 262144
#define WOFF_C 393216
#define WOFF_X 458752
#define WOFF_U 753664
__device__ __nv_bfloat16 g_WT_hi[1048576];
__device__ __nv_bfloat16 g_WT_lo[1048576];

// ---------------- scalar helpers ----------------
__device__ __forceinline__ float sigmf(float x) {
    return __fdividef(1.f, 1.f + __expf(-x));
}
__device__ __forceinline__ float tanh_fast(float x) {
    float ax = fabsf(x);
    float e = __expf(-2.f * ax);
    return copysignf(__fdividef(1.f - e, 1.f + e), x);
}
// {lo=bf16_trunc(a_fp32bits), hi=bf16_trunc(b_fp32bits)}
__device__ __forceinline__ u32 hipack(u32 a, u32 b) {
    u32 d;
    asm("prmt.b32 %0, %1, %2, 0x7632;" : "=r"(d) : "r"(a), "r"(b));
    return d;
}
#define PACKBF2(r, a, b) \
    asm("cvt.rn.satfinite.bf16x2.f32 %0, %1, %2;" : "=r"(r) : "f"(b), "f"(a))

#define MMA_BF16(c, a0, a1, a2, a3, b0, b1) \
    asm volatile("mma.sync.aligned.m16n8k16.row.col.f32.bf16.bf16.f32 " \
        "{%0,%1,%2,%3}, {%4,%5,%6,%7}, {%8,%9}, {%0,%1,%2,%3};" \
        : "+f"((c)[0]), "+f"((c)[1]), "+f"((c)[2]), "+f"((c)[3]) \
        : "r"(a0), "r"(a1), "r"(a2), "r"(a3), "r"(b0), "r"(b1))

// ---------------- 0) transpose + split ALL weights (one launch) --------------
__global__ void wsplit_all(const float* __restrict__ Wd, const float* __restrict__ Wg,
                           const float* __restrict__ Wc, const float* __restrict__ gW,
                           const float* __restrict__ gU)
{
    int y = blockIdx.y;
    const float* src;
    int dstoff, K, N;
    if (y == 0)      { src = Wd; dstoff = WOFF_D; K = 2048; N = 128; }
    else if (y == 1) { src = Wg; dstoff = WOFF_G; K = 1024; N = 128; }
    else if (y == 2) { src = Wc; dstoff = WOFF_C; K = 512;  N = 128; }
    else if (y < 9)  { int lt = y - 3; src = gW + (size_t)lt * 49152;
                       dstoff = WOFF_X + lt * 49152; K = 128; N = 384; }
    else             { int lt = y - 9; src = gU + (size_t)lt * 49152;
                       dstoff = WOFF_U + lt * 49152; K = 128; N = 384; }
    __nv_bfloat16* hi = g_WT_hi + dstoff;
    __nv_bfloat16* lo = g_WT_lo + dstoff;
    int total = K * N;
    for (int i = blockIdx.x * blockDim.x + threadIdx.x; i < total; i += gridDim.x * blockDim.x) {
        int k = i / N, n = i - k * N;
        float w = src[i];
        u32 u = __float_as_uint(w);
        __nv_bfloat16_raw hr; hr.x = (unsigned short)(u >> 16);
        hi[(size_t)n * K + k] = __nv_bfloat16(hr);
        lo[(size_t)n * K + k] = __float2bfloat16(w - __uint_as_float(u & 0xffff0000u));
    }
}

// ---------------- 1) proj: all 3 tables in ONE grid (R14 passing) ------------
__global__ __launch_bounds__(256, 2) void proj_mma(
    const float* __restrict__ drug, const float* __restrict__ gene,
    const float* __restrict__ cell,
    const float* __restrict__ bd, const float* __restrict__ bg,
    const float* __restrict__ bc)
{
    extern __shared__ u32 sm32[];
    u32* sAh = sm32;               // 128*36
    u32* sAl = sAh + 4608;
    u32* sBh = sAl + 4608;
    u32* sBl = sBh + 4608;

    int bx = blockIdx.x;
    const float *F, *bias;
    float* E;
    int N, K, woff, bstart;
    if (bx < 157)      { F = drug; bias = bd; E = g_E_drug; N = ND; K = 2048; woff = WOFF_D; bstart = bx; }
    else if (bx < 314) { F = gene; bias = bg; E = g_E_gene; N = NG; K = 1024; woff = WOFF_G; bstart = bx - 157; }
    else               { F = cell; bias = bc; E = g_E_cell; N = NC; K = 512;  woff = WOFF_C; bstart = bx - 314; }
    const __nv_bfloat16* WTh = g_WT_hi + woff;
    const __nv_bfloat16* WTl = g_WT_lo + woff;

    int tid = threadIdx.x, wm = tid >> 5, lane = tid & 31;
    int g = lane >> 2, t = lane & 3;
    int row0 = bstart * 128;

    float acc[16][4];
#pragma unroll
    for (int j = 0; j < 16; j++)
#pragma unroll
        for (int q = 0; q < 4; q++) acc[j][q] = 0.f;

    int srow = tid >> 1, skh = (tid & 1) * 32;
    int aclamp = row0 + srow < N ? row0 + srow : N - 1;
    const float* Abase = F + (size_t)aclamp * K;

    for (int kc = 0; kc < K; kc += 64) {
        __syncthreads();
        {
            const float4* src = (const float4*)(Abase + kc + skh);
            u32* dh = sAh + srow * 36 + (skh >> 1);
            u32* dl = sAl + srow * 36 + (skh >> 1);
#pragma unroll
            for (int i = 0; i < 8; i++) {
                float4 f = src[i];
                u32 ux = __float_as_uint(f.x), uy = __float_as_uint(f.y);
                u32 uz = __float_as_uint(f.z), uw = __float_as_uint(f.w);
                dh[i * 2]     = hipack(ux, uy);
                dh[i * 2 + 1] = hipack(uz, uw);
                float lx = f.x - __uint_as_float(ux & 0xffff0000u);
                float ly = f.y - __uint_as_float(uy & 0xffff0000u);
                float lz = f.z - __uint_as_float(uz & 0xffff0000u);
                float lw = f.w - __uint_as_float(uw & 0xffff0000u);
                u32 l0, l1;
                PACKBF2(l0, lx, ly);
                PACKBF2(l1, lz, lw);
                dl[i * 2] = l0; dl[i * 2 + 1] = l1;
            }
        }
        {
            const uint4* bh = (const uint4*)(WTh + (size_t)srow * K + kc + skh);
            const uint4* bl = (const uint4*)(WTl + (size_t)srow * K + kc + skh);
            uint4* dh = (uint4*)(sBh + srow * 36 + (skh >> 1));
            uint4* dl = (uint4*)(sBl + srow * 36 + (skh >> 1));
#pragma unroll
            for (int i = 0; i < 4; i++) { dh[i] = bh[i]; dl[i] = bl[i]; }
        }
        __syncthreads();

#pragma unroll
        for (int ks = 0; ks < 4; ks++) {
            int ab = (wm * 16 + g) * 36 + ks * 8 + t;
            u32 ah0 = sAh[ab],       ah1 = sAh[ab + 288];
            u32 ah2 = sAh[ab + 4],   ah3 = sAh[ab + 292];
            u32 al0 = sAl[ab],       al1 = sAl[ab + 288];
            u32 al2 = sAl[ab + 4],   al3 = sAl[ab + 292];
#pragma unroll
            for (int j = 0; j < 16; j++) {
                int bb = (j * 8 + g) * 36 + ks * 8 + t;
                u32 bh0 = sBh[bb], bh1 = sBh[bb + 4];
                u32 bl0 = sBl[bb], bl1 = sBl[bb + 4];
                MMA_BF16(acc[j], ah0, ah1, ah2, ah3, bh0, bh1);
                MMA_BF16(acc[j], al0, al1, al2, al3, bh0, bh1);
                MMA_BF16(acc[j], ah0, ah1, ah2, ah3, bl0, bl1);
            }
        }
    }

    int r0 = row0 + wm * 16 + g;
#pragma unroll
    for (int j = 0; j < 16; j++) {
        int col = j * 8 + 2 * t;
        float bx2 = bias[col], by = bias[col + 1];
        if (r0 < N)
            *(float2*)(E + (size_t)r0 * 128 + col) =
                make_float2(acc[j][0] + bx2, acc[j][1] + by);
        if (r0 + 8 < N)
            *(float2*)(E + (size_t)(r0 + 8) * 128 + col) =
                make_float2(acc[j][2] + bx2, acc[j][3] + by);
    }
}

// ---------------- 2) xw: LAYER-MERGED (R14 passing) ---------------------------
__global__ __launch_bounds__(256, 2) void xw_mma(
    const float* __restrict__ gruB,
    const int* __restrict__ nd, const int* __restrict__ ng,
    const int* __restrict__ pnc)
{
    extern __shared__ u32 sm32[];
    u32* sAh = sm32;               // 128*68
    u32* sAl = sAh + 8704;
    u32* sBh = sAl + 8704;         // 64*68
    u32* sBl = sBh + 4352;

    int tid = threadIdx.x, wm = tid >> 5, lane = tid & 31;
    int g = lane >> 2, t = lane & 3;
    int t3 = blockIdx.y;
    const int* nbr = (t3 == 0) ? nd : (t3 == 1) ? ng : pnc;
    const float* Etab = (t3 == 0) ? g_E_drug : (t3 == 1) ? g_E_gene : g_E_cell;
    int row0 = blockIdx.x * 128;

    {   // stage A (gathered, K=128) ONCE for both layers
        int srow = tid >> 1, skh = (tid & 1) * 64;
        int id = nbr[row0 + srow];
        bool v = (id >= 0);
        const float4* src = (const float4*)(Etab + (size_t)(v ? id : 0) * 128 + skh);
        u32* dh = sAh + srow * 68 + (skh >> 1);
        u32* dl = sAl + srow * 68 + (skh >> 1);
#pragma unroll
        for (int i = 0; i < 16; i++) {
            float4 f = v ? src[i] : make_float4(0.f, 0.f, 0.f, 0.f);
            u32 ux = __float_as_uint(f.x), uy = __float_as_uint(f.y);
            u32 uz = __float_as_uint(f.z), uw = __float_as_uint(f.w);
            dh[i * 2]     = hipack(ux, uy);
            dh[i * 2 + 1] = hipack(uz, uw);
            float lx = f.x - __uint_as_float(ux & 0xffff0000u);
            float ly = f.y - __uint_as_float(uy & 0xffff0000u);
            float lz = f.z - __uint_as_float(uz & 0xffff0000u);
            float lw = f.w - __uint_as_float(uw & 0xffff0000u);
            u32 l0, l1;
            PACKBF2(l0, lx, ly);
            PACKBF2(l1, lz, lw);
            dl[i * 2] = l0; dl[i * 2 + 1] = l1;
        }
    }

#pragma unroll
    for (int l = 0; l < 2; l++) {
        int lt = l * 3 + t3;
        const __nv_bfloat16* WTh = g_WT_hi + WOFF_X + lt * 49152;
        const __nv_bfloat16* WTl = g_WT_lo + WOFF_X + lt * 49152;
        const float* bias = gruB + lt * 384;
        float* out = g_XW + (size_t)lt * 40960 * 384;

        for (int ncb = 0; ncb < 6; ncb++) {
            __syncthreads();
            {
                int brow = tid >> 2, kq = (tid & 3) * 32;
                const uint4* bh = (const uint4*)(WTh + (size_t)(ncb * 64 + brow) * 128 + kq);
                const uint4* bl = (const uint4*)(WTl + (size_t)(ncb * 64 + brow) * 128 + kq);
                uint4* dh = (uint4*)(sBh + brow * 68 + (kq >> 1));
                uint4* dl = (uint4*)(sBl + brow * 68 + (kq >> 1));
#pragma unroll
                for (int i = 0; i < 4; i++) { dh[i] = bh[i]; dl[i] = bl[i]; }
            }
            __syncthreads();

            float acc[8][4];
#pragma unroll
            for (int j = 0; j < 8; j++)
#pragma unroll
                for (int q = 0; q < 4; q++) acc[j][q] = 0.f;

#pragma unroll
            for (int ks = 0; ks < 8; ks++) {
                int ab = (wm * 16 + g) * 68 + ks * 8 + t;
                u32 ah0 = sAh[ab],     ah1 = sAh[ab + 544];
                u32 ah2 = sAh[ab + 4], ah3 = sAh[ab + 548];
                u32 al0 = sAl[ab],     al1 = sAl[ab + 544];
                u32 al2 = sAl[ab + 4], al3 = sAl[ab + 548];
#pragma unroll
                for (int j = 0; j < 8; j++) {
                    int bb = (j * 8 + g) * 68 + ks * 8 + t;
                    u32 bh0 = sBh[bb], bh1 = sBh[bb + 4];
                    u32 bl0 = sBl[bb], bl1 = sBl[bb + 4];
                    MMA_BF16(acc[j], ah0, ah1, ah2, ah3, bh0, bh1);
                    MMA_BF16(acc[j], al0, al1, al2, al3, bh0, bh1);
                    MMA_BF16(acc[j], ah0, ah1, ah2, ah3, bl0, bl1);
                }
            }

            int r0 = row0 + wm * 16 + g;
#pragma unroll
            for (int j = 0; j < 8; j++) {
                int col = ncb * 64 + j * 8 + 2 * t;
                float bx = bias[col], by = bias[col + 1];
                *(float2*)(out + (size_t)r0 * 384 + col) =
                    make_float2(acc[j][0] + bx, acc[j][1] + by);
                *(float2*)(out + (size_t)(r0 + 8) * 384 + col) =
                    make_float2(acc[j][2] + bx, acc[j][3] + by);
            }
        }
    }
}

// ---------------- 3) GRU — fragment-major U + DOUBLE-BUFFERED H ---------------
// H_s lives in buf[s&1]; step s reads buf[(s-1)&1], writes buf[s&1].
// Read/write sets disjoint -> ONE __syncthreads per step (was two).
__global__ __launch_bounds__(512, 1) void gru_mma(
    const int* __restrict__ nd, const int* __restrict__ ng,
    const int* __restrict__ pnc)
{
    extern __shared__ u32 sg[];
    u32* sU  = sg;                  // 49152 u32 (U hi+lo fragment-major)
    u32* sH  = sU + 49152;          // 4 buffers: [buf][hi/lo] x 2048 u32 each
    float* sM = (float*)(sH + 8192);    // 320
    float* sCnt = sM + 320;             // 32

    int tid = threadIdx.x, wm = tid >> 5, lane = tid & 31;
    int g = lane >> 2, t = lane & 3;
    int lt = blockIdx.y, t3 = lt % 3;
    const int* nbr = (t3 == 0) ? nd : (t3 == 1) ? ng : pnc;
    int b0 = blockIdx.x * 32;
    const uint4* UTh = (const uint4*)(g_WT_hi + WOFF_U + lt * 49152);
    const uint4* UTl = (const uint4*)(g_WT_lo + WOFF_U + lt * 49152);

    for (int i = tid; i < 6144; i += 512) {
        int n = i >> 4;
        int q = i & 15;
        uint4 vh = UTh[i];
        uint4 vl = UTl[i];
        int n8 = n >> 3, gg = n & 7, ks = q >> 1, c = q & 1;
        u32 base = (u32)((n8 * 8 + ks) * 32 + gg * 4) * 4 + c;
        sU[base + 0]  = vh.x; sU[base + 4]  = vh.y;
        sU[base + 8]  = vh.z; sU[base + 12] = vh.w;
        sU[base + 2]  = vl.x; sU[base + 6]  = vl.y;
        sU[base + 10] = vl.z; sU[base + 14] = vl.w;
    }
    for (int i = tid; i < 320; i += 512) {
        int rr = i / 10, s = i % 10;
        sM[i] = (nbr[(size_t)(b0 + rr) * 10 + s] >= 0) ? 1.f : 0.f;
    }
    for (int i = tid; i < 8192; i += 512) sH[i] = 0u;
    __syncthreads();
    if (tid < 32) {
        float c = 0.f;
        for (int s = 0; s < 10; s++) c += sM[tid * 10 + s];
        sCnt[tid] = fmaxf(c, 1.f);
    }
    __syncthreads();

    int ksp = wm >> 1;
    int cb  = (wm & 1) * 2;

    float hreg[2][4], msum[2][4];
#pragma unroll
    for (int mi = 0; mi < 2; mi++)
#pragma unroll
        for (int q = 0; q < 4; q++) { hreg[mi][q] = 0.f; msum[mi][q] = 0.f; }

    for (int s = 0; s < 10; s++) {
        u32* rb = sH + ((s + 1) & 1) * 4096;   // buf[(s-1)&1]: hi at +0, lo at +2048
        u32* wb = sH + (s & 1) * 4096;         // buf[s&1]

        float2 xz[2][2], xr[2][2], xn[2][2];
        int d0 = 8 * wm + 2 * t;
#pragma unroll
        for (int mi = 0; mi < 2; mi++)
#pragma unroll
            for (int rh = 0; rh < 2; rh++) {
                int lrow = mi * 16 + g + rh * 8;
                const float* xwb = g_XW +
                    ((size_t)lt * 40960 + (size_t)(b0 + lrow) * 10 + s) * 384;
                xz[mi][rh] = *(const float2*)(xwb + d0);
                xr[mi][rh] = *(const float2*)(xwb + 128 + d0);
                xn[mi][rh] = *(const float2*)(xwb + 256 + d0);
            }

        float acc[2][3][4];
#pragma unroll
        for (int mi = 0; mi < 2; mi++)
#pragma unroll
            for (int j = 0; j < 3; j++)
#pragma unroll
                for (int q = 0; q < 4; q++) acc[mi][j][q] = 0.f;

#pragma unroll
        for (int ks = 0; ks < 8; ks++) {
            uint4 afh[2], afl[2];
#pragma unroll
            for (int mi = 0; mi < 2; mi++) {
                u32 ab = (u32)((mi * 8 + ks) * 32 + lane) * 4;
                afh[mi] = *(const uint4*)(rb + ab);
                afl[mi] = *(const uint4*)(rb + 2048 + ab);
            }
#pragma unroll
            for (int j = 0; j < 3; j++) {
                int n8 = j * 16 + wm;
                uint4 bf = *(const uint4*)(sU + (u32)((n8 * 8 + ks) * 32 + lane) * 4);
#pragma unroll
                for (int mi = 0; mi < 2; mi++) {
                    MMA_BF16(acc[mi][j], afh[mi].x, afh[mi].y, afh[mi].z, afh[mi].w, bf.x, bf.y);
                    MMA_BF16(acc[mi][j], afl[mi].x, afl[mi].y, afl[mi].z, afl[mi].w, bf.x, bf.y);
                    MMA_BF16(acc[mi][j], afh[mi].x, afh[mi].y, afh[mi].z, afh[mi].w, bf.z, bf.w);
                }
            }
        }
        // no barrier here: reads hit rb, writes hit wb (disjoint)

#pragma unroll
        for (int mi = 0; mi < 2; mi++)
#pragma unroll
            for (int rh = 0; rh < 2; rh++) {
                int q0 = rh * 2;
                int lrow = mi * 16 + g + rh * 8;
                float2 vz = xz[mi][rh], vr = xr[mi][rh], vn = xn[mi][rh];
                float z0 = sigmf(vz.x + acc[mi][0][q0]);
                float z1 = sigmf(vz.y + acc[mi][0][q0 + 1]);
                float r0 = sigmf(vr.x + acc[mi][1][q0]);
                float r1 = sigmf(vr.y + acc[mi][1][q0 + 1]);
                float n0 = tanh_fast(vn.x + r0 * acc[mi][2][q0]);
                float n1 = tanh_fast(vn.y + r1 * acc[mi][2][q0 + 1]);
                float h0 = (1.f - z0) * n0 + z0 * hreg[mi][q0];
                float h1 = (1.f - z1) * n1 + z1 * hreg[mi][q0 + 1];
                hreg[mi][q0] = h0;
                hreg[mi][q0 + 1] = h1;
                float mk = sM[lrow * 10 + s];
                msum[mi][q0]     += mk * h0;
                msum[mi][q0 + 1] += mk * h1;
                u32 u0 = __float_as_uint(h0), u1 = __float_as_uint(h1);
                u32 hi = hipack(u0, u1);
                float l0f = h0 - __uint_as_float(u0 & 0xffff0000u);
                float l1f = h1 - __uint_as_float(u1 & 0xffff0000u);
                u32 lo;
                PACKBF2(lo, l0f, l1f);
                u32 hidx = (u32)((mi * 8 + ksp) * 32 + lane) * 4 + cb + rh;
                wb[hidx] = hi;
                wb[2048 + hidx] = lo;
            }
        __syncthreads();   // writes to wb visible before next step reads it
    }

    int d0 = 8 * wm + 2 * t;
#pragma unroll
    for (int mi = 0; mi < 2; mi++)
#pragma unroll
        for (int rh = 0; rh < 2; rh++) {
            int q0 = rh * 2;
            int lrow = mi * 16 + g + rh * 8;
            float invc = 1.f / sCnt[lrow];
            *(float2*)(g_S + ((size_t)lt * BB + b0 + lrow) * 128 + d0) =
                make_float2(msum[mi][q0] * invc, msum[mi][q0 + 1] * invc);
        }
}

// ---------------- 4) attention combine — shuffle reductions ------------------
__global__ __launch_bounds__(128) void final_kernel(
    const float* __restrict__ att, const int* __restrict__ ids,
    float* __restrict__ out)
{
    __shared__ float red[20];
    __shared__ float sC[3][128];
    int b = blockIdx.x, d = threadIdx.x;
    int w = d >> 5, lane = d & 31;
    float h = g_E_drug[(size_t)ids[b] * 128 + d];
#pragma unroll
    for (int l = 0; l < 2; l++) {
        for (int t = 0; t < 3; t++)
            sC[t][d] = g_S[((size_t)(l * 3 + t) * BB + b) * 128 + d];
        __syncthreads();
        float a1 = att[l * 256 + d], a2 = att[l * 256 + 128 + d];
        float p0 = h * a1, p1 = h * a2;
        float p2 = sC[0][d] * a2, p3 = sC[1][d] * a2, p4 = sC[2][d] * a2;
#pragma unroll
        for (int st = 16; st > 0; st >>= 1) {
            p0 += __shfl_xor_sync(0xffffffffu, p0, st);
            p1 += __shfl_xor_sync(0xffffffffu, p1, st);
            p2 += __shfl_xor_sync(0xffffffffu, p2, st);
            p3 += __shfl_xor_sync(0xffffffffu, p3, st);
            p4 += __shfl_xor_sync(0xffffffffu, p4, st);
        }
        if (lane == 0) {
            red[w] = p0; red[4 + w] = p1; red[8 + w] = p2;
            red[12 + w] = p3; red[16 + w] = p4;
        }
        __syncthreads();
        float dh1 = red[0] + red[1] + red[2] + red[3];
        float dh2 = red[4] + red[5] + red[6] + red[7];
        float c1 = red[8] + red[9] + red[10] + red[11];
        float c2 = red[12] + red[13] + red[14] + red[15];
        float c3 = red[16] + red[17] + red[18] + red[19];
        float e0 = dh1 + dh2, e1 = dh1 + c1, e2 = dh1 + c2, e3 = dh1 + c3;
        e0 = e0 > 0.f ? e0 : 0.01f * e0;
        e1 = e1 > 0.f ? e1 : 0.01f * e1;
        e2 = e2 > 0.f ? e2 : 0.01f * e2;
        e3 = e3 > 0.f ? e3 : 0.01f * e3;
        float mx = fmaxf(fmaxf(e0, e1), fmaxf(e2, e3));
        float w0 = __expf(e0 - mx), w1 = __expf(e1 - mx);
        float w2 = __expf(e2 - mx), w3 = __expf(e3 - mx);
        float inv = __fdividef(1.f, w0 + w1 + w2 + w3);
        h = (w0 * h + w1 * sC[0][d] + w2 * sC[1][d] + w3 * sC[2][d]) * inv;
        __syncthreads();
    }
    out[(size_t)b * 128 + d] = h;
}

// ---------------- launch ----------------
extern "C" void kernel_launch(void* const* d_in, const int* in_sizes, int n_in,
                              void* d_out, int out_size)
{
    const float* drug = (const float*)d_in[0];
    const float* gene = (const float*)d_in[1];
    const float* cell = (const float*)d_in[2];
    const float* Wd = (const float*)d_in[3];
    const float* bd = (const float*)d_in[4];
    const float* Wg = (const float*)d_in[5];
    const float* bg = (const float*)d_in[6];
    const float* Wc = (const float*)d_in[7];
    const float* bc = (const float*)d_in[8];
    const float* gW = (const float*)d_in[9];
    const float* gU = (const float*)d_in[10];
    const float* gb = (const float*)d_in[11];
    const float* att = (const float*)d_in[12];
    const int* ids = (const int*)d_in[13];
    const int* nd = (const int*)d_in[14];
    const int* ng = (const int*)d_in[15];
    const int* nc = (const int*)d_in[16];
    float* out = (float*)d_out;

    const int PROJ_SMEM = 4 * 4608 * 4;                 // 73728
    const int XW_SMEM   = (2 * 8704 + 2 * 4352) * 4;    // 104448
    const int GRUM_SMEM = (49152 + 8192 + 352) * 4;     // 230784
    cudaFuncSetAttribute(proj_mma, cudaFuncAttributeMaxDynamicSharedMemorySize, PROJ_SMEM);
    cudaFuncSetAttribute(xw_mma, cudaFuncAttributeMaxDynamicSharedMemorySize, XW_SMEM);
    cudaFuncSetAttribute(gru_mma, cudaFuncAttributeMaxDynamicSharedMemorySize, GRUM_SMEM);

    // 0) weight transpose + bf16 split (all, one launch)
    wsplit_all<<<dim3(32, 15), 256>>>(Wd, Wg, Wc, gW, gU);

    // 1) project all 3 tables (one grid)
    proj_mma<<<393, 256, PROJ_SMEM>>>(drug, gene, cell, bd, bg, bc);

    // 2) XW = gathered E @ gru_W + gru_b (layer-merged)
    xw_mma<<<dim3(320, 3), 256, XW_SMEM>>>(gb, nd, ng, nc);

    // 3) GRU recurrence + masked mean (double-buffered H, 1 barrier/step)
    gru_mma<<<dim3(BB / 32, 6), 512, GRUM_SMEM>>>(nd, ng, nc);

    // 4) attention combine + output
    final_kernel<<<BB, 128>>>(att, ids, out);
}

// round 17
// speedup vs baseline: 1.0766x; 1.0151x over previous
#include <cuda_runtime.h>
#include <cuda_bf16.h>

typedef unsigned long long u64;
typedef unsigned u32;

#define ND 20000
#define NG 20000
#define NC 10000
#define BB 4096

__device__ float g_E_drug[ND * 128];
__device__ float g_E_gene[NG * 128];
__device__ float g_E_cell[NC * 128];
__device__ float g_XW[6 * BB * 10 * 384];
__device__ float g_S[6 * BB * 128];
// transposed bf16-split weights [N][K]: [d | g | c | x(6) | u(6)]
#define WOFF_D 0
#define WOFF_G 262144
#define WOFF_C 393216
#define WOFF_X 458752
#define WOFF_U 753664
__device__ __nv_bfloat16 g_WT_hi[1048576];
__device__ __nv_bfloat16 g_WT_lo[1048576];

// ---------------- scalar helpers ----------------
__device__ __forceinline__ float sigmf(float x) {
    return __fdividef(1.f, 1.f + __expf(-x));
}
__device__ __forceinline__ float tanh_fast(float x) {
    float ax = fabsf(x);
    float e = __expf(-2.f * ax);
    return copysignf(__fdividef(1.f - e, 1.f + e), x);
}
// {lo=bf16_trunc(a_fp32bits), hi=bf16_trunc(b_fp32bits)}
__device__ __forceinline__ u32 hipack(u32 a, u32 b) {
    u32 d;
    asm("prmt.b32 %0, %1, %2, 0x7632;" : "=r"(d) : "r"(a), "r"(b));
    return d;
}
#define PACKBF2(r, a, b) \
    asm("cvt.rn.satfinite.bf16x2.f32 %0, %1, %2;" : "=r"(r) : "f"(b), "f"(a))

#define MMA_BF16(c, a0, a1, a2, a3, b0, b1) \
    asm volatile("mma.sync.aligned.m16n8k16.row.col.f32.bf16.bf16.f32 " \
        "{%0,%1,%2,%3}, {%4,%5,%6,%7}, {%8,%9}, {%0,%1,%2,%3};" \
        : "+f"((c)[0]), "+f"((c)[1]), "+f"((c)[2]), "+f"((c)[3]) \
        : "r"(a0), "r"(a1), "r"(a2), "r"(a3), "r"(b0), "r"(b1))

// ---------------- 0) transpose + split ALL weights (one launch) --------------
__global__ void wsplit_all(const float* __restrict__ Wd, const float* __restrict__ Wg,
                           const float* __restrict__ Wc, const float* __restrict__ gW,
                           const float* __restrict__ gU)
{
    int y = blockIdx.y;
    const float* src;
    int dstoff, K, N;
    if (y == 0)      { src = Wd; dstoff = WOFF_D; K = 2048; N = 128; }
    else if (y == 1) { src = Wg; dstoff = WOFF_G; K = 1024; N = 128; }
    else if (y == 2) { src = Wc; dstoff = WOFF_C; K = 512;  N = 128; }
    else if (y < 9)  { int lt = y - 3; src = gW + (size_t)lt * 49152;
                       dstoff = WOFF_X + lt * 49152; K = 128; N = 384; }
    else             { int lt = y - 9; src = gU + (size_t)lt * 49152;
                       dstoff = WOFF_U + lt * 49152; K = 128; N = 384; }
    __nv_bfloat16* hi = g_WT_hi + dstoff;
    __nv_bfloat16* lo = g_WT_lo + dstoff;
    int total = K * N;
    for (int i = blockIdx.x * blockDim.x + threadIdx.x; i < total; i += gridDim.x * blockDim.x) {
        int k = i / N, n = i - k * N;
        float w = src[i];
        u32 u = __float_as_uint(w);
        __nv_bfloat16_raw hr; hr.x = (unsigned short)(u >> 16);
        hi[(size_t)n * K + k] = __nv_bfloat16(hr);
        lo[(size_t)n * K + k] = __float2bfloat16(w - __uint_as_float(u & 0xffff0000u));
    }
}

// ---------------- 1) proj: all 3 tables in ONE grid (R14 passing) ------------
__global__ __launch_bounds__(256, 2) void proj_mma(
    const float* __restrict__ drug, const float* __restrict__ gene,
    const float* __restrict__ cell,
    const float* __restrict__ bd, const float* __restrict__ bg,
    const float* __restrict__ bc)
{
    extern __shared__ u32 sm32[];
    u32* sAh = sm32;               // 128*36
    u32* sAl = sAh + 4608;
    u32* sBh = sAl + 4608;
    u32* sBl = sBh + 4608;

    int bx = blockIdx.x;
    const float *F, *bias;
    float* E;
    int N, K, woff, bstart;
    if (bx < 157)      { F = drug; bias = bd; E = g_E_drug; N = ND; K = 2048; woff = WOFF_D; bstart = bx; }
    else if (bx < 314) { F = gene; bias = bg; E = g_E_gene; N = NG; K = 1024; woff = WOFF_G; bstart = bx - 157; }
    else               { F = cell; bias = bc; E = g_E_cell; N = NC; K = 512;  woff = WOFF_C; bstart = bx - 314; }
    const __nv_bfloat16* WTh = g_WT_hi + woff;
    const __nv_bfloat16* WTl = g_WT_lo + woff;

    int tid = threadIdx.x, wm = tid >> 5, lane = tid & 31;
    int g = lane >> 2, t = lane & 3;
    int row0 = bstart * 128;

    float acc[16][4];
#pragma unroll
    for (int j = 0; j < 16; j++)
#pragma unroll
        for (int q = 0; q < 4; q++) acc[j][q] = 0.f;

    int srow = tid >> 1, skh = (tid & 1) * 32;
    int aclamp = row0 + srow < N ? row0 + srow : N - 1;
    const float* Abase = F + (size_t)aclamp * K;

    for (int kc = 0; kc < K; kc += 64) {
        __syncthreads();
        {
            const float4* src = (const float4*)(Abase + kc + skh);
            u32* dh = sAh + srow * 36 + (skh >> 1);
            u32* dl = sAl + srow * 36 + (skh >> 1);
#pragma unroll
            for (int i = 0; i < 8; i++) {
                float4 f = src[i];
                u32 ux = __float_as_uint(f.x), uy = __float_as_uint(f.y);
                u32 uz = __float_as_uint(f.z), uw = __float_as_uint(f.w);
                dh[i * 2]     = hipack(ux, uy);
                dh[i * 2 + 1] = hipack(uz, uw);
                float lx = f.x - __uint_as_float(ux & 0xffff0000u);
                float ly = f.y - __uint_as_float(uy & 0xffff0000u);
                float lz = f.z - __uint_as_float(uz & 0xffff0000u);
                float lw = f.w - __uint_as_float(uw & 0xffff0000u);
                u32 l0, l1;
                PACKBF2(l0, lx, ly);
                PACKBF2(l1, lz, lw);
                dl[i * 2] = l0; dl[i * 2 + 1] = l1;
            }
        }
        {
            const uint4* bh = (const uint4*)(WTh + (size_t)srow * K + kc + skh);
            const uint4* bl = (const uint4*)(WTl + (size_t)srow * K + kc + skh);
            uint4* dh = (uint4*)(sBh + srow * 36 + (skh >> 1));
            uint4* dl = (uint4*)(sBl + srow * 36 + (skh >> 1));
#pragma unroll
            for (int i = 0; i < 4; i++) { dh[i] = bh[i]; dl[i] = bl[i]; }
        }
        __syncthreads();

#pragma unroll
        for (int ks = 0; ks < 4; ks++) {
            int ab = (wm * 16 + g) * 36 + ks * 8 + t;
            u32 ah0 = sAh[ab],       ah1 = sAh[ab + 288];
            u32 ah2 = sAh[ab + 4],   ah3 = sAh[ab + 292];
            u32 al0 = sAl[ab],       al1 = sAl[ab + 288];
            u32 al2 = sAl[ab + 4],   al3 = sAl[ab + 292];
#pragma unroll
            for (int j = 0; j < 16; j++) {
                int bb = (j * 8 + g) * 36 + ks * 8 + t;
                u32 bh0 = sBh[bb], bh1 = sBh[bb + 4];
                u32 bl0 = sBl[bb], bl1 = sBl[bb + 4];
                MMA_BF16(acc[j], ah0, ah1, ah2, ah3, bh0, bh1);
                MMA_BF16(acc[j], al0, al1, al2, al3, bh0, bh1);
                MMA_BF16(acc[j], ah0, ah1, ah2, ah3, bl0, bl1);
            }
        }
    }

    int r0 = row0 + wm * 16 + g;
#pragma unroll
    for (int j = 0; j < 16; j++) {
        int col = j * 8 + 2 * t;
        float bx2 = bias[col], by = bias[col + 1];
        if (r0 < N)
            *(float2*)(E + (size_t)r0 * 128 + col) =
                make_float2(acc[j][0] + bx2, acc[j][1] + by);
        if (r0 + 8 < N)
            *(float2*)(E + (size_t)(r0 + 8) * 128 + col) =
                make_float2(acc[j][2] + bx2, acc[j][3] + by);
    }
}

// ---------------- 2) xw: LAYER-MERGED (R14 passing) ---------------------------
__global__ __launch_bounds__(256, 2) void xw_mma(
    const float* __restrict__ gruB,
    const int* __restrict__ nd, const int* __restrict__ ng,
    const int* __restrict__ pnc)
{
    extern __shared__ u32 sm32[];
    u32* sAh = sm32;               // 128*68
    u32* sAl = sAh + 8704;
    u32* sBh = sAl + 8704;         // 64*68
    u32* sBl = sBh + 4352;

    int tid = threadIdx.x, wm = tid >> 5, lane = tid & 31;
    int g = lane >> 2, t = lane & 3;
    int t3 = blockIdx.y;
    const int* nbr = (t3 == 0) ? nd : (t3 == 1) ? ng : pnc;
    const float* Etab = (t3 == 0) ? g_E_drug : (t3 == 1) ? g_E_gene : g_E_cell;
    int row0 = blockIdx.x * 128;

    {   // stage A (gathered, K=128) ONCE for both layers
        int srow = tid >> 1, skh = (tid & 1) * 64;
        int id = nbr[row0 + srow];
        bool v = (id >= 0);
        const float4* src = (const float4*)(Etab + (size_t)(v ? id : 0) * 128 + skh);
        u32* dh = sAh + srow * 68 + (skh >> 1);
        u32* dl = sAl + srow * 68 + (skh >> 1);
#pragma unroll
        for (int i = 0; i < 16; i++) {
            float4 f = v ? src[i] : make_float4(0.f, 0.f, 0.f, 0.f);
            u32 ux = __float_as_uint(f.x), uy = __float_as_uint(f.y);
            u32 uz = __float_as_uint(f.z), uw = __float_as_uint(f.w);
            dh[i * 2]     = hipack(ux, uy);
            dh[i * 2 + 1] = hipack(uz, uw);
            float lx = f.x - __uint_as_float(ux & 0xffff0000u);
            float ly = f.y - __uint_as_float(uy & 0xffff0000u);
            float lz = f.z - __uint_as_float(uz & 0xffff0000u);
            float lw = f.w - __uint_as_float(uw & 0xffff0000u);
            u32 l0, l1;
            PACKBF2(l0, lx, ly);
            PACKBF2(l1, lz, lw);
            dl[i * 2] = l0; dl[i * 2 + 1] = l1;
        }
    }

#pragma unroll
    for (int l = 0; l < 2; l++) {
        int lt = l * 3 + t3;
        const __nv_bfloat16* WTh = g_WT_hi + WOFF_X + lt * 49152;
        const __nv_bfloat16* WTl = g_WT_lo + WOFF_X + lt * 49152;
        const float* bias = gruB + lt * 384;
        float* out = g_XW + (size_t)lt * 40960 * 384;

        for (int ncb = 0; ncb < 6; ncb++) {
            __syncthreads();
            {
                int brow = tid >> 2, kq = (tid & 3) * 32;
                const uint4* bh = (const uint4*)(WTh + (size_t)(ncb * 64 + brow) * 128 + kq);
                const uint4* bl = (const uint4*)(WTl + (size_t)(ncb * 64 + brow) * 128 + kq);
                uint4* dh = (uint4*)(sBh + brow * 68 + (kq >> 1));
                uint4* dl = (uint4*)(sBl + brow * 68 + (kq >> 1));
#pragma unroll
                for (int i = 0; i < 4; i++) { dh[i] = bh[i]; dl[i] = bl[i]; }
            }
            __syncthreads();

            float acc[8][4];
#pragma unroll
            for (int j = 0; j < 8; j++)
#pragma unroll
                for (int q = 0; q < 4; q++) acc[j][q] = 0.f;

#pragma unroll
            for (int ks = 0; ks < 8; ks++) {
                int ab = (wm * 16 + g) * 68 + ks * 8 + t;
                u32 ah0 = sAh[ab],     ah1 = sAh[ab + 544];
                u32 ah2 = sAh[ab + 4], ah3 = sAh[ab + 548];
                u32 al0 = sAl[ab],     al1 = sAl[ab + 544];
                u32 al2 = sAl[ab + 4], al3 = sAl[ab + 548];
#pragma unroll
                for (int j = 0; j < 8; j++) {
                    int bb = (j * 8 + g) * 68 + ks * 8 + t;
                    u32 bh0 = sBh[bb], bh1 = sBh[bb + 4];
                    u32 bl0 = sBl[bb], bl1 = sBl[bb + 4];
                    MMA_BF16(acc[j], ah0, ah1, ah2, ah3, bh0, bh1);
                    MMA_BF16(acc[j], al0, al1, al2, al3, bh0, bh1);
                    MMA_BF16(acc[j], ah0, ah1, ah2, ah3, bl0, bl1);
                }
            }

            int r0 = row0 + wm * 16 + g;
#pragma unroll
            for (int j = 0; j < 8; j++) {
                int col = ncb * 64 + j * 8 + 2 * t;
                float bx = bias[col], by = bias[col + 1];
                *(float2*)(out + (size_t)r0 * 384 + col) =
                    make_float2(acc[j][0] + bx, acc[j][1] + by);
                *(float2*)(out + (size_t)(r0 + 8) * 384 + col) =
                    make_float2(acc[j][2] + bx, acc[j][3] + by);
            }
        }
    }
}

// ---------------- 3) GRU recurrence — fragment-major U + H (R14 EXACT) -------
__global__ __launch_bounds__(512, 1) void gru_mma(
    const int* __restrict__ nd, const int* __restrict__ ng,
    const int* __restrict__ pnc)
{
    extern __shared__ u32 sg[];
    u32* sU  = sg;                  // 49152 u32 (U hi+lo fragment-major)
    u32* sAh = sU + 49152;          // 2048 (H hi fragment-major)
    u32* sAl = sAh + 2048;          // 2048
    float* sM = (float*)(sAl + 2048);   // 320
    float* sCnt = sM + 320;             // 32

    int tid = threadIdx.x, wm = tid >> 5, lane = tid & 31;
    int g = lane >> 2, t = lane & 3;
    int lt = blockIdx.y, t3 = lt % 3;
    const int* nbr = (t3 == 0) ? nd : (t3 == 1) ? ng : pnc;
    int b0 = blockIdx.x * 32;
    const uint4* UTh = (const uint4*)(g_WT_hi + WOFF_U + lt * 49152);
    const uint4* UTl = (const uint4*)(g_WT_lo + WOFF_U + lt * 49152);

    for (int i = tid; i < 6144; i += 512) {
        int n = i >> 4;
        int q = i & 15;
        uint4 vh = UTh[i];
        uint4 vl = UTl[i];
        int n8 = n >> 3, gg = n & 7, ks = q >> 1, c = q & 1;
        u32 base = (u32)((n8 * 8 + ks) * 32 + gg * 4) * 4 + c;
        sU[base + 0]  = vh.x; sU[base + 4]  = vh.y;
        sU[base + 8]  = vh.z; sU[base + 12] = vh.w;
        sU[base + 2]  = vl.x; sU[base + 6]  = vl.y;
        sU[base + 10] = vl.z; sU[base + 14] = vl.w;
    }
    for (int i = tid; i < 320; i += 512) {
        int rr = i / 10, s = i % 10;
        sM[i] = (nbr[(size_t)(b0 + rr) * 10 + s] >= 0) ? 1.f : 0.f;
    }
    for (int i = tid; i < 2048; i += 512) { sAh[i] = 0u; sAl[i] = 0u; }
    __syncthreads();
    if (tid < 32) {
        float c = 0.f;
        for (int s = 0; s < 10; s++) c += sM[tid * 10 + s];
        sCnt[tid] = fmaxf(c, 1.f);
    }
    __syncthreads();

    int ksp = wm >> 1;
    int cb  = (wm & 1) * 2;

    float hreg[2][4], msum[2][4];
#pragma unroll
    for (int mi = 0; mi < 2; mi++)
#pragma unroll
        for (int q = 0; q < 4; q++) { hreg[mi][q] = 0.f; msum[mi][q] = 0.f; }

    for (int s = 0; s < 10; s++) {
        float2 xz[2][2], xr[2][2], xn[2][2];
        int d0 = 8 * wm + 2 * t;
#pragma unroll
        for (int mi = 0; mi < 2; mi++)
#pragma unroll
            for (int rh = 0; rh < 2; rh++) {
                int lrow = mi * 16 + g + rh * 8;
                const float* xwb = g_XW +
                    ((size_t)lt * 40960 + (size_t)(b0 + lrow) * 10 + s) * 384;
                xz[mi][rh] = *(const float2*)(xwb + d0);
                xr[mi][rh] = *(const float2*)(xwb + 128 + d0);
                xn[mi][rh] = *(const float2*)(xwb + 256 + d0);
            }

        float acc[2][3][4];
#pragma unroll
        for (int mi = 0; mi < 2; mi++)
#pragma unroll
            for (int j = 0; j < 3; j++)
#pragma unroll
                for (int q = 0; q < 4; q++) acc[mi][j][q] = 0.f;

#pragma unroll
        for (int ks = 0; ks < 8; ks++) {
            uint4 afh[2], afl[2];
#pragma unroll
            for (int mi = 0; mi < 2; mi++) {
                u32 ab = (u32)((mi * 8 + ks) * 32 + lane) * 4;
                afh[mi] = *(const uint4*)(sAh + ab);
                afl[mi] = *(const uint4*)(sAl + ab);
            }
#pragma unroll
            for (int j = 0; j < 3; j++) {
                int n8 = j * 16 + wm;
                uint4 bf = *(const uint4*)(sU + (u32)((n8 * 8 + ks) * 32 + lane) * 4);
#pragma unroll
                for (int mi = 0; mi < 2; mi++) {
                    MMA_BF16(acc[mi][j], afh[mi].x, afh[mi].y, afh[mi].z, afh[mi].w, bf.x, bf.y);
                    MMA_BF16(acc[mi][j], afl[mi].x, afl[mi].y, afl[mi].z, afl[mi].w, bf.x, bf.y);
                    MMA_BF16(acc[mi][j], afh[mi].x, afh[mi].y, afh[mi].z, afh[mi].w, bf.z, bf.w);
                }
            }
        }
        __syncthreads();

#pragma unroll
        for (int mi = 0; mi < 2; mi++)
#pragma unroll
            for (int rh = 0; rh < 2; rh++) {
                int q0 = rh * 2;
                int lrow = mi * 16 + g + rh * 8;
                float2 vz = xz[mi][rh], vr = xr[mi][rh], vn = xn[mi][rh];
                float z0 = sigmf(vz.x + acc[mi][0][q0]);
                float z1 = sigmf(vz.y + acc[mi][0][q0 + 1]);
                float r0 = sigmf(vr.x + acc[mi][1][q0]);
                float r1 = sigmf(vr.y + acc[mi][1][q0 + 1]);
                float n0 = tanh_fast(vn.x + r0 * acc[mi][2][q0]);
                float n1 = tanh_fast(vn.y + r1 * acc[mi][2][q0 + 1]);
                float h0 = (1.f - z0) * n0 + z0 * hreg[mi][q0];
                float h1 = (1.f - z1) * n1 + z1 * hreg[mi][q0 + 1];
                hreg[mi][q0] = h0;
                hreg[mi][q0 + 1] = h1;
                float mk = sM[lrow * 10 + s];
                msum[mi][q0]     += mk * h0;
                msum[mi][q0 + 1] += mk * h1;
                u32 u0 = __float_as_uint(h0), u1 = __float_as_uint(h1);
                u32 hi = hipack(u0, u1);
                float l0f = h0 - __uint_as_float(u0 & 0xffff0000u);
                float l1f = h1 - __uint_as_float(u1 & 0xffff0000u);
                u32 lo;
                PACKBF2(lo, l0f, l1f);
                u32 hidx = (u32)((mi * 8 + ksp) * 32 + lane) * 4 + cb + rh;
                sAh[hidx] = hi;
                sAl[hidx] = lo;
            }
        __syncthreads();
    }

    int d0 = 8 * wm + 2 * t;
#pragma unroll
    for (int mi = 0; mi < 2; mi++)
#pragma unroll
        for (int rh = 0; rh < 2; rh++) {
            int q0 = rh * 2;
            int lrow = mi * 16 + g + rh * 8;
            float invc = 1.f / sCnt[lrow];
            *(float2*)(g_S + ((size_t)lt * BB + b0 + lrow) * 128 + d0) =
                make_float2(msum[mi][q0] * invc, msum[mi][q0 + 1] * invc);
        }
}

// ---------------- 4) attention combine — 4 batches per 512-thr block ---------
__global__ __launch_bounds__(512) void final_kernel(
    const float* __restrict__ att, const int* __restrict__ ids,
    float* __restrict__ out)
{
    __shared__ float red[4][20];
    __shared__ float sC[4][3][128];
    int sub = threadIdx.x >> 7;          // 0..3 (batch within block)
    int d = threadIdx.x & 127;
    int b = blockIdx.x * 4 + sub;
    int w = d >> 5, lane = d & 31;
    float h = g_E_drug[(size_t)ids[b] * 128 + d];
#pragma unroll
    for (int l = 0; l < 2; l++) {
        for (int t = 0; t < 3; t++)
            sC[sub][t][d] = g_S[((size_t)(l * 3 + t) * BB + b) * 128 + d];
        __syncthreads();
        float a1 = att[l * 256 + d], a2 = att[l * 256 + 128 + d];
        float p0 = h * a1, p1 = h * a2;
        float p2 = sC[sub][0][d] * a2, p3 = sC[sub][1][d] * a2, p4 = sC[sub][2][d] * a2;
#pragma unroll
        for (int st = 16; st > 0; st >>= 1) {
            p0 += __shfl_xor_sync(0xffffffffu, p0, st);
            p1 += __shfl_xor_sync(0xffffffffu, p1, st);
            p2 += __shfl_xor_sync(0xffffffffu, p2, st);
            p3 += __shfl_xor_sync(0xffffffffu, p3, st);
            p4 += __shfl_xor_sync(0xffffffffu, p4, st);
        }
        if (lane == 0) {
            red[sub][w] = p0; red[sub][4 + w] = p1; red[sub][8 + w] = p2;
            red[sub][12 + w] = p3; red[sub][16 + w] = p4;
        }
        __syncthreads();
        float dh1 = red[sub][0] + red[sub][1] + red[sub][2] + red[sub][3];
        float dh2 = red[sub][4] + red[sub][5] + red[sub][6] + red[sub][7];
        float c1 = red[sub][8] + red[sub][9] + red[sub][10] + red[sub][11];
        float c2 = red[sub][12] + red[sub][13] + red[sub][14] + red[sub][15];
        float c3 = red[sub][16] + red[sub][17] + red[sub][18] + red[sub][19];
        float e0 = dh1 + dh2, e1 = dh1 + c1, e2 = dh1 + c2, e3 = dh1 + c3;
        e0 = e0 > 0.f ? e0 : 0.01f * e0;
        e1 = e1 > 0.f ? e1 : 0.01f * e1;
        e2 = e2 > 0.f ? e2 : 0.01f * e2;
        e3 = e3 > 0.f ? e3 : 0.01f * e3;
        float mx = fmaxf(fmaxf(e0, e1), fmaxf(e2, e3));
        float w0 = __expf(e0 - mx), w1 = __expf(e1 - mx);
        float w2 = __expf(e2 - mx), w3 = __expf(e3 - mx);
        float inv = __fdividef(1.f, w0 + w1 + w2 + w3);
        h = (w0 * h + w1 * sC[sub][0][d] + w2 * sC[sub][1][d] + w3 * sC[sub][2][d]) * inv;
        __syncthreads();
    }
    out[(size_t)b * 128 + d] = h;
}

// ---------------- launch ----------------
extern "C" void kernel_launch(void* const* d_in, const int* in_sizes, int n_in,
                              void* d_out, int out_size)
{
    const float* drug = (const float*)d_in[0];
    const float* gene = (const float*)d_in[1];
    const float* cell = (const float*)d_in[2];
    const float* Wd = (const float*)d_in[3];
    const float* bd = (const float*)d_in[4];
    const float* Wg = (const float*)d_in[5];
    const float* bg = (const float*)d_in[6];
    const float* Wc = (const float*)d_in[7];
    const float* bc = (const float*)d_in[8];
    const float* gW = (const float*)d_in[9];
    const float* gU = (const float*)d_in[10];
    const float* gb = (const float*)d_in[11];
    const float* att = (const float*)d_in[12];
    const int* ids = (const int*)d_in[13];
    const int* nd = (const int*)d_in[14];
    const int* ng = (const int*)d_in[15];
    const int* nc = (const int*)d_in[16];
    float* out = (float*)d_out;

    const int PROJ_SMEM = 4 * 4608 * 4;                 // 73728
    const int XW_SMEM   = (2 * 8704 + 2 * 4352) * 4;    // 104448
    const int GRUM_SMEM = (49152 + 2 * 2048 + 352) * 4; // 214400
    cudaFuncSetAttribute(proj_mma, cudaFuncAttributeMaxDynamicSharedMemorySize, PROJ_SMEM);
    cudaFuncSetAttribute(xw_mma, cudaFuncAttributeMaxDynamicSharedMemorySize, XW_SMEM);
    cudaFuncSetAttribute(gru_mma, cudaFuncAttributeMaxDynamicSharedMemorySize, GRUM_SMEM);

    // 0) weight transpose + bf16 split (all, one launch)
    wsplit_all<<<dim3(32, 15), 256>>>(Wd, Wg, Wc, gW, gU);

    // 1) project all 3 tables (one grid)
    proj_mma<<<393, 256, PROJ_SMEM>>>(drug, gene, cell, bd, bg, bc);

    // 2) XW = gathered E @ gru_W + gru_b (layer-merged)
    xw_mma<<<dim3(320, 3), 256, XW_SMEM>>>(gb, nd, ng, nc);

    // 3) GRU recurrence + masked mean (fragment-major U + H, R14)
    gru_mma<<<dim3(BB / 32, 6), 512, GRUM_SMEM>>>(nd, ng, nc);

    // 4) attention combine + output (4 batches/block)
    final_kernel<<<BB / 4, 512>>>(att, ids, out);
}